// round 1
// baseline (speedup 1.0000x reference)
#include <cuda_runtime.h>
#include <cstdint>

#define DIM    256
#define BT_MAX 32768
#define N_MAX  2048

#define BM 128
#define BN 128
#define BK 16
#define PAD 4

// Scratch (no allocations allowed in kernel_launch)
__device__ float g_c2[N_MAX];
__device__ int   g_idx[BT_MAX];
__device__ float g_partial[BT_MAX];
__device__ float g_dummy[BT_MAX + 1];

// ---------------------------------------------------------------------------
// Kernel 1: c2[n] = ||codebook[n]||^2. One warp per code row.
// ---------------------------------------------------------------------------
__global__ void c2_kernel(const float* __restrict__ cb, int N) {
    int warp = (blockIdx.x * blockDim.x + threadIdx.x) >> 5;
    int lane = threadIdx.x & 31;
    if (warp >= N) return;
    const float4* row = (const float4*)(cb + (size_t)warp * DIM);
    float s = 0.f;
#pragma unroll
    for (int i = 0; i < 2; i++) {
        float4 v = row[lane + i * 32];
        s += v.x * v.x + v.y * v.y + v.z * v.z + v.w * v.w;
    }
#pragma unroll
    for (int o = 16; o > 0; o >>= 1) s += __shfl_xor_sync(0xffffffffu, s, o);
    if (lane == 0) g_c2[warp] = s;
}

// ---------------------------------------------------------------------------
// Kernel 2: fused SGEMM + argmin.
// score(t, n) = c2[n] - 2 * dot(x[t], cb[n])   (x2 is row-constant -> dropped)
// 128x128 tile, BK=16, 256 threads, 8x8 register tiles.
// ---------------------------------------------------------------------------
__global__ void __launch_bounds__(256)
argmin_kernel(const float* __restrict__ x, const float* __restrict__ cb,
              int BT, int N) {
    __shared__ float As[BK][BM + PAD];
    __shared__ float Bs[BK][BN + PAD];
    __shared__ float sv[BM][16];
    __shared__ int   si[BM][16];

    const int tid  = threadIdx.x;
    const int m0   = blockIdx.x * BM;
    const int rowb = (tid >> 4) * 8;   // 16 row-groups of 8 rows
    const int colb = (tid & 15) * 8;   // 16 col-groups of 8 cols

    float bestv[8];
    int   besti[8];
#pragma unroll
    for (int i = 0; i < 8; i++) { bestv[i] = 3.4e38f; besti[i] = 0; }

    for (int n0 = 0; n0 < N; n0 += BN) {
        float acc[8][8];
#pragma unroll
        for (int i = 0; i < 8; i++)
#pragma unroll
            for (int j = 0; j < 8; j++) acc[i][j] = 0.f;

        for (int k0 = 0; k0 < DIM; k0 += BK) {
            // Stage A (x) and B (codebook) tiles, transposed to [k][m]/[k][n].
#pragma unroll
            for (int l = 0; l < 2; l++) {
                int li  = tid + l * 256;
                int row = li >> 2;
                int c4  = li & 3;
                float4 v = *(const float4*)(x  + (size_t)(m0 + row) * DIM + k0 + c4 * 4);
                As[c4 * 4 + 0][row] = v.x;
                As[c4 * 4 + 1][row] = v.y;
                As[c4 * 4 + 2][row] = v.z;
                As[c4 * 4 + 3][row] = v.w;
                float4 w = *(const float4*)(cb + (size_t)(n0 + row) * DIM + k0 + c4 * 4);
                Bs[c4 * 4 + 0][row] = w.x;
                Bs[c4 * 4 + 1][row] = w.y;
                Bs[c4 * 4 + 2][row] = w.z;
                Bs[c4 * 4 + 3][row] = w.w;
            }
            __syncthreads();
#pragma unroll
            for (int k = 0; k < BK; k++) {
                float a[8], b[8];
                *(float4*)&a[0] = *(const float4*)&As[k][rowb];
                *(float4*)&a[4] = *(const float4*)&As[k][rowb + 4];
                *(float4*)&b[0] = *(const float4*)&Bs[k][colb];
                *(float4*)&b[4] = *(const float4*)&Bs[k][colb + 4];
#pragma unroll
                for (int i = 0; i < 8; i++)
#pragma unroll
                    for (int j = 0; j < 8; j++)
                        acc[i][j] = fmaf(a[i], b[j], acc[i][j]);
            }
            __syncthreads();
        }

        // Per-tile argmin epilogue
        float c2r[8];
#pragma unroll
        for (int j = 0; j < 8; j++) c2r[j] = g_c2[n0 + colb + j];
#pragma unroll
        for (int i = 0; i < 8; i++) {
#pragma unroll
            for (int j = 0; j < 8; j++) {
                float s  = fmaf(-2.f, acc[i][j], c2r[j]);
                int   ii = n0 + colb + j;
                if (s < bestv[i] || (s == bestv[i] && ii < besti[i])) {
                    bestv[i] = s;
                    besti[i] = ii;
                }
            }
        }
    }

    // Cross-thread reduction: 16 lanes carry candidates per row.
#pragma unroll
    for (int i = 0; i < 8; i++) {
        sv[rowb + i][tid & 15] = bestv[i];
        si[rowb + i][tid & 15] = besti[i];
    }
    __syncthreads();
    if (tid < BM) {
        float bv = sv[tid][0];
        int   bi = si[tid][0];
#pragma unroll
        for (int l = 1; l < 16; l++) {
            float v  = sv[tid][l];
            int   ii = si[tid][l];
            if (v < bv || (v == bv && ii < bi)) { bv = v; bi = ii; }
        }
        g_idx[m0 + tid] = bi;
    }
}

// ---------------------------------------------------------------------------
// Kernel 3: gather codes -> out, per-token SSE partial, indices as float.
// One block (256 threads) per token; thread = one dim element.
// ---------------------------------------------------------------------------
__global__ void gather_kernel(const float* __restrict__ x,
                              const float* __restrict__ cb,
                              float* __restrict__ out_q,
                              float* __restrict__ out_idx) {
    __shared__ float red[8];
    const int t   = blockIdx.x;
    const int tid = threadIdx.x;
    const int idx = g_idx[t];

    float c  = cb[(size_t)idx * DIM + tid];
    float xv = x [(size_t)t   * DIM + tid];
    out_q[(size_t)t * DIM + tid] = c;

    float d = xv - c;
    d = d * d;
#pragma unroll
    for (int o = 16; o > 0; o >>= 1) d += __shfl_xor_sync(0xffffffffu, d, o);
    if ((tid & 31) == 0) red[tid >> 5] = d;
    __syncthreads();
    if (tid == 0) {
        float s = 0.f;
#pragma unroll
        for (int w = 0; w < 8; w++) s += red[w];
        g_partial[t] = s;
        out_idx[t]   = (float)idx;
    }
}

// ---------------------------------------------------------------------------
// Kernel 4: deterministic tree reduction of partials -> loss scalar.
// loss = code_loss + commitment*embedding_loss = 2 * mean((x - codes)^2)
// ---------------------------------------------------------------------------
__global__ void loss_kernel(float* __restrict__ out_loss, int BT, float inv_count) {
    __shared__ float red[1024];
    float s = 0.f;
    for (int i = threadIdx.x; i < BT; i += 1024) s += g_partial[i];
    red[threadIdx.x] = s;
    __syncthreads();
    for (int o = 512; o > 0; o >>= 1) {
        if (threadIdx.x < o) red[threadIdx.x] += red[threadIdx.x + o];
        __syncthreads();
    }
    if (threadIdx.x == 0) *out_loss = 2.f * red[0] * inv_count;
}

// ---------------------------------------------------------------------------
extern "C" void kernel_launch(void* const* d_in, const int* in_sizes, int n_in,
                              void* d_out, int out_size) {
    const float* x  = (const float*)d_in[0];
    const float* cb = (const float*)d_in[1];
    float* out = (float*)d_out;

    const int BT = in_sizes[0] / DIM;   // 32768
    const int N  = in_sizes[1] / DIM;   // 2048

    // Output layout: [quantized BT*DIM | indices BT | loss 1]
    const long long need = (long long)BT * DIM + BT + 1;
    const bool full_layout = ((long long)out_size >= need);

    float* out_idx  = full_layout ? (out + (size_t)BT * DIM) : g_dummy;
    float* out_loss = full_layout ? (out + (size_t)BT * DIM + BT) : (g_dummy + BT_MAX);

    c2_kernel<<<(N + 7) / 8, 256>>>(cb, N);
    argmin_kernel<<<BT / BM, 256>>>(x, cb, BT, N);
    gather_kernel<<<BT, 256>>>(x, cb, out, out_idx);
    loss_kernel<<<1, 1024>>>(out_loss, BT, 1.f / ((float)BT * (float)DIM));
}

// round 3
// speedup vs baseline: 3.5229x; 3.5229x over previous
#include <cuda_runtime.h>
#include <cuda_bf16.h>
#include <cstdint>

#define DIM    256
#define BT     32768
#define NCODE  2048
#define MARGIN 1.0f

// ---------------------------------------------------------------------------
// Device scratch (static; no allocations allowed)
// ---------------------------------------------------------------------------
__device__ __nv_bfloat16 g_xb [(size_t)BT * DIM];      // 16 MB
__device__ __nv_bfloat16 g_cbb[(size_t)NCODE * DIM];   // 1 MB
__device__ float g_dot[(size_t)BT * NCODE];            // 256 MB
__device__ float g_c2[NCODE];
__device__ float g_partial[BT];
__device__ float g_dummy[BT + 1];

// ---------------------------------------------------------------------------
// Helpers
// ---------------------------------------------------------------------------
__device__ __forceinline__ uint32_t smem_u32(const void* p) {
    uint32_t a;
    asm("{ .reg .u64 t; cvta.to.shared.u64 t, %1; cvt.u32.u64 %0, t; }"
        : "=r"(a) : "l"(p));
    return a;
}

#define SWZ(o) ((o) ^ (((o) >> 3) & 0x70))

__device__ __forceinline__ void cp16(uint32_t d, const void* s) {
    asm volatile("cp.async.cg.shared.global [%0], [%1], 16;\n"
                 :: "r"(d), "l"(__cvta_generic_to_global(s)));
}
__device__ __forceinline__ void cp_commit() {
    asm volatile("cp.async.commit_group;\n" ::: "memory");
}
template <int N> __device__ __forceinline__ void cp_wait() {
    asm volatile("cp.async.wait_group %0;\n" :: "n"(N) : "memory");
}

__device__ __forceinline__ void ldm_x4(uint32_t& r0, uint32_t& r1,
                                       uint32_t& r2, uint32_t& r3, uint32_t a) {
    asm volatile("ldmatrix.sync.aligned.m8n8.x4.shared.b16 {%0,%1,%2,%3}, [%4];"
                 : "=r"(r0), "=r"(r1), "=r"(r2), "=r"(r3) : "r"(a));
}

__device__ __forceinline__ void mma_bf16(float* d, uint32_t a0, uint32_t a1,
                                         uint32_t a2, uint32_t a3,
                                         uint32_t b0, uint32_t b1) {
    asm volatile(
        "mma.sync.aligned.m16n8k16.row.col.f32.bf16.bf16.f32 "
        "{%0,%1,%2,%3}, {%4,%5,%6,%7}, {%8,%9}, {%0,%1,%2,%3};"
        : "+f"(d[0]), "+f"(d[1]), "+f"(d[2]), "+f"(d[3])
        : "r"(a0), "r"(a1), "r"(a2), "r"(a3), "r"(b0), "r"(b1));
}

// ---------------------------------------------------------------------------
// Elementwise fp32 -> bf16 (vectorized x4)
// ---------------------------------------------------------------------------
__global__ void tobf16_kernel(const float* __restrict__ in,
                              __nv_bfloat16* __restrict__ outp, int n4) {
    int i = blockIdx.x * blockDim.x + threadIdx.x;
    if (i >= n4) return;
    float4 v = ((const float4*)in)[i];
    __nv_bfloat162 lo = __floats2bfloat162_rn(v.x, v.y);
    __nv_bfloat162 hi = __floats2bfloat162_rn(v.z, v.w);
    ((__nv_bfloat162*)outp)[2 * i]     = lo;
    ((__nv_bfloat162*)outp)[2 * i + 1] = hi;
}

// ---------------------------------------------------------------------------
// c2[n] = ||codebook[n]||^2 (fp32, exact). One warp per code row.
// ---------------------------------------------------------------------------
__global__ void c2_kernel(const float* __restrict__ cb, int N) {
    int warp = (blockIdx.x * blockDim.x + threadIdx.x) >> 5;
    int lane = threadIdx.x & 31;
    if (warp >= N) return;
    const float4* row = (const float4*)(cb + (size_t)warp * DIM);
    float s = 0.f;
#pragma unroll
    for (int i = 0; i < 2; i++) {
        float4 v = row[lane + i * 32];
        s += v.x * v.x + v.y * v.y + v.z * v.z + v.w * v.w;
    }
#pragma unroll
    for (int o = 16; o > 0; o >>= 1) s += __shfl_xor_sync(0xffffffffu, s, o);
    if (lane == 0) g_c2[warp] = s;
}

// ---------------------------------------------------------------------------
// bf16 HMMA GEMM: dot[m, n] = x_bf16[m, :] . cb_bf16[n, :]  (fp32 accum)
// 128x128 tile per CTA, K=256 fully prefetched in 4 cp.async chunks (128 KB).
// 8 warps as 4(M) x 2(N); warp tile 32x64 via m16n8k16.
// ---------------------------------------------------------------------------
__global__ void __launch_bounds__(256, 1)
dot_mma_kernel(float* __restrict__ dout) {
    extern __shared__ char sm[];
    const uint32_t sbase = smem_u32(sm);
    const int tid  = threadIdx.x;
    const int wid  = tid >> 5;
    const int lane = tid & 31;
    const int m0   = blockIdx.x * 128;
    const int n0   = blockIdx.y * 128;
    const int wm   = (wid & 3) * 32;    // warp M offset
    const int wn   = (wid >> 2) * 64;   // warp N offset

    // Issue all 4 K-chunk loads (A: 128x64 bf16, B: 128x64 bf16 per chunk)
#pragma unroll
    for (int c = 0; c < 4; c++) {
        uint32_t ab = sbase + c * 32768;
        uint32_t bb = ab + 16384;
#pragma unroll
        for (int i = 0; i < 4; i++) {
            int idx = tid + (i << 8);      // 0..1023
            int r   = idx >> 3;            // row 0..127
            int c16 = idx & 7;             // 16B column
            uint32_t off = SWZ((uint32_t)(r * 128 + c16 * 16));
            cp16(ab + off, g_xb  + (size_t)(m0 + r) * DIM + c * 64 + c16 * 8);
            cp16(bb + off, g_cbb + (size_t)(n0 + r) * DIM + c * 64 + c16 * 8);
        }
        cp_commit();
    }

    float acc[2][8][4];
#pragma unroll
    for (int i = 0; i < 2; i++)
#pragma unroll
        for (int j = 0; j < 8; j++)
#pragma unroll
            for (int k = 0; k < 4; k++) acc[i][j][k] = 0.f;

    const int lrow = lane & 15;
    const int lcol = (lane >> 4) << 4;

#pragma unroll
    for (int c = 0; c < 4; c++) {
        if (c == 0) cp_wait<3>();
        else if (c == 1) cp_wait<2>();
        else if (c == 2) cp_wait<1>();
        else cp_wait<0>();
        __syncthreads();

        uint32_t ab = sbase + c * 32768;
        uint32_t bb = ab + 16384;
#pragma unroll
        for (int kk = 0; kk < 4; kk++) {
            int colb = kk * 32 + lcol;
            uint32_t a0[4], a1[4], br[4][4];
            ldm_x4(a0[0], a0[1], a0[2], a0[3],
                   ab + SWZ((uint32_t)((wm + lrow) * 128 + colb)));
            ldm_x4(a1[0], a1[1], a1[2], a1[3],
                   ab + SWZ((uint32_t)((wm + 16 + lrow) * 128 + colb)));
#pragma unroll
            for (int jn = 0; jn < 4; jn++)
                ldm_x4(br[jn][0], br[jn][1], br[jn][2], br[jn][3],
                       bb + SWZ((uint32_t)((wn + jn * 16 + lrow) * 128 + colb)));
#pragma unroll
            for (int jn = 0; jn < 4; jn++) {
                mma_bf16(acc[0][jn * 2],     a0[0], a0[1], a0[2], a0[3], br[jn][0], br[jn][2]);
                mma_bf16(acc[0][jn * 2 + 1], a0[0], a0[1], a0[2], a0[3], br[jn][1], br[jn][3]);
                mma_bf16(acc[1][jn * 2],     a1[0], a1[1], a1[2], a1[3], br[jn][0], br[jn][2]);
                mma_bf16(acc[1][jn * 2 + 1], a1[0], a1[1], a1[2], a1[3], br[jn][1], br[jn][3]);
            }
        }
    }

    // Epilogue: write fp32 dots (st.global.v2)
    const int g  = lane >> 2;
    const int tg = lane & 3;
#pragma unroll
    for (int im = 0; im < 2; im++)
#pragma unroll
        for (int j8 = 0; j8 < 8; j8++) {
            size_t row = (size_t)(m0 + wm + im * 16 + g);
            size_t col = (size_t)(n0 + wn + j8 * 8 + tg * 2);
            *(float2*)(dout + row * NCODE + col) =
                make_float2(acc[im][j8][0], acc[im][j8][1]);
            *(float2*)(dout + (row + 8) * NCODE + col) =
                make_float2(acc[im][j8][2], acc[im][j8][3]);
        }
}

// ---------------------------------------------------------------------------
// Select: per token, min over approx scores, exact fp32 rescore of candidates
// within MARGIN, then fused gather + SSE partial. One 256-thread block/token.
// ---------------------------------------------------------------------------
__global__ void __launch_bounds__(256)
select_kernel(const float* __restrict__ x, const float* __restrict__ cb,
              float* __restrict__ out_q, float* __restrict__ out_idx) {
    __shared__ float xs[DIM];
    __shared__ float smin[8];
    __shared__ int   scand[64];
    __shared__ int   scount;
    __shared__ unsigned long long sbest;

    const int t = blockIdx.x, tid = threadIdx.x;
    const int wid = tid >> 5, lane = tid & 31;

    xs[tid] = x[(size_t)t * DIM + tid];
    if (tid == 0) { scount = 0; sbest = ~0ull; }
    __syncthreads();

    // approx scores for 8 codes per thread
    const float4* dr  = (const float4*)(g_dot + (size_t)t * NCODE);
    const float4* c2v = (const float4*)g_c2;
    float4 d0 = dr[tid * 2], d1 = dr[tid * 2 + 1];
    float4 q0 = c2v[tid * 2], q1 = c2v[tid * 2 + 1];
    float s[8];
    s[0] = q0.x - 2.f * d0.x; s[1] = q0.y - 2.f * d0.y;
    s[2] = q0.z - 2.f * d0.z; s[3] = q0.w - 2.f * d0.w;
    s[4] = q1.x - 2.f * d1.x; s[5] = q1.y - 2.f * d1.y;
    s[6] = q1.z - 2.f * d1.z; s[7] = q1.w - 2.f * d1.w;

    float mn = s[0];
#pragma unroll
    for (int i = 1; i < 8; i++) mn = fminf(mn, s[i]);
#pragma unroll
    for (int o = 16; o > 0; o >>= 1)
        mn = fminf(mn, __shfl_xor_sync(0xffffffffu, mn, o));
    if (lane == 0) smin[wid] = mn;
    __syncthreads();
    if (tid == 0) {
        float m = smin[0];
#pragma unroll
        for (int w = 1; w < 8; w++) m = fminf(m, smin[w]);
        smin[0] = m;
    }
    __syncthreads();
    const float thr = smin[0] + MARGIN;

#pragma unroll
    for (int i = 0; i < 8; i++) {
        if (s[i] < thr) {
            int p = atomicAdd(&scount, 1);
            if (p < 64) scand[p] = tid * 8 + i;
        }
    }
    __syncthreads();
    const int cnt = scount;

    // exact fp32 rescore: one warp per candidate
    const bool overflow = (cnt > 64);
    const int  ncand    = overflow ? NCODE : cnt;
    for (int ci = wid; ci < ncand; ci += 8) {
        int n = overflow ? ci : scand[ci];
        const float* crow = cb + (size_t)n * DIM;
        float dot = 0.f;
#pragma unroll
        for (int j = 0; j < 8; j++)
            dot = fmaf(xs[lane + j * 32], crow[lane + j * 32], dot);
#pragma unroll
        for (int o = 16; o > 0; o >>= 1)
            dot += __shfl_xor_sync(0xffffffffu, dot, o);
        if (lane == 0) {
            float sv = g_c2[n] - 2.f * dot;
            uint32_t b = __float_as_uint(sv);
            uint32_t key32 = (b & 0x80000000u) ? ~b : (b | 0x80000000u);
            unsigned long long key =
                ((unsigned long long)key32 << 32) | (uint32_t)n;
            atomicMin(&sbest, key);
        }
    }
    __syncthreads();
    const int best = (int)(sbest & 0xFFFFFFFFull);

    // fused gather + SSE partial
    float c = cb[(size_t)best * DIM + tid];
    out_q[(size_t)t * DIM + tid] = c;
    float d = xs[tid] - c;
    d = d * d;
#pragma unroll
    for (int o = 16; o > 0; o >>= 1) d += __shfl_xor_sync(0xffffffffu, d, o);
    if (lane == 0) smin[wid] = d;
    __syncthreads();
    if (tid == 0) {
        float ssum = 0.f;
#pragma unroll
        for (int w = 0; w < 8; w++) ssum += smin[w];
        g_partial[t] = ssum;
        out_idx[t]   = (float)best;
    }
}

// ---------------------------------------------------------------------------
// Deterministic loss reduction. loss = 2 * mean((x - codes)^2)
// ---------------------------------------------------------------------------
__global__ void loss_kernel(float* __restrict__ out_loss, int N, float inv_count) {
    __shared__ float red[1024];
    float s = 0.f;
    for (int i = threadIdx.x; i < N; i += 1024) s += g_partial[i];
    red[threadIdx.x] = s;
    __syncthreads();
    for (int o = 512; o > 0; o >>= 1) {
        if (threadIdx.x < o) red[threadIdx.x] += red[threadIdx.x + o];
        __syncthreads();
    }
    if (threadIdx.x == 0) *out_loss = 2.f * red[0] * inv_count;
}

// ---------------------------------------------------------------------------
extern "C" void kernel_launch(void* const* d_in, const int* in_sizes, int n_in,
                              void* d_out, int out_size) {
    const float* x  = (const float*)d_in[0];
    const float* cb = (const float*)d_in[1];
    float* out = (float*)d_out;

    const int bt = in_sizes[0] / DIM;   // 32768
    const int nc = in_sizes[1] / DIM;   // 2048

    const long long need = (long long)bt * DIM + bt + 1;
    const bool full_layout = ((long long)out_size >= need);
    float* out_idx  = full_layout ? (out + (size_t)bt * DIM) : g_dummy;
    float* out_loss = full_layout ? (out + (size_t)bt * DIM + bt) : (g_dummy + BT);

    __nv_bfloat16* xb;  cudaGetSymbolAddress((void**)&xb,  g_xb);
    __nv_bfloat16* cbb; cudaGetSymbolAddress((void**)&cbb, g_cbb);
    float* dotp;        cudaGetSymbolAddress((void**)&dotp, g_dot);

    const int nx4 = bt * DIM / 4;
    const int nc4 = nc * DIM / 4;
    tobf16_kernel<<<(nx4 + 255) / 256, 256>>>(x,  xb,  nx4);
    tobf16_kernel<<<(nc4 + 255) / 256, 256>>>(cb, cbb, nc4);
    c2_kernel<<<(nc + 7) / 8, 256>>>(cb, nc);

    cudaFuncSetAttribute(dot_mma_kernel,
                         cudaFuncAttributeMaxDynamicSharedMemorySize, 131072);
    dim3 grid(bt / 128, nc / 128);
    dot_mma_kernel<<<grid, 256, 131072>>>(dotp);

    select_kernel<<<bt, 256>>>(x, cb, out, out_idx);
    loss_kernel<<<1, 1024>>>(out_loss, bt, 1.f / ((float)bt * (float)DIM));
}

// round 4
// speedup vs baseline: 4.6613x; 1.3231x over previous
#include <cuda_runtime.h>
#include <cuda_bf16.h>
#include <cstdint>

#define DIM     256
#define BT      32768
#define NCODE   2048
#define MARGIN  1.0f
#define CAP     32
#define M_CTA   128
#define N_TILES (NCODE / 128)      // 16

// smem layout (relative to 1KB-aligned base)
#define OFF_A      0               // 128 x 256 bf16 = 64 KB (4 planes of 16KB)
#define OFF_B      65536           // 2 stages x 64 KB
#define OFF_KEY    196608          // u32[128]
#define OFF_CNT    197120          // int[128]
#define OFF_CAND   197632          // int[128][CAP] = 16 KB
#define SMEM_BYTES (197632 + 128 * CAP * 4 + 1024)   // + align slack

// ---------------------------------------------------------------------------
// Device scratch
// ---------------------------------------------------------------------------
__device__ __nv_bfloat16 g_cbb[(size_t)NCODE * DIM];   // 1 MB
__device__ float g_c2[NCODE];
__device__ int   g_flag[BT];
__device__ float g_partial[BT];
__device__ float g_dummy[BT + 1];

// ---------------------------------------------------------------------------
// Helpers
// ---------------------------------------------------------------------------
__device__ __forceinline__ uint32_t smem_u32(const void* p) {
    uint32_t a;
    asm("{ .reg .u64 t; cvta.to.shared.u64 t, %1; cvt.u32.u64 %0, t; }"
        : "=r"(a) : "l"(p));
    return a;
}

#define SWZ(o) ((o) ^ (((o) >> 3) & 0x70))

__device__ __forceinline__ void cp16(uint32_t d, const void* s) {
    asm volatile("cp.async.cg.shared.global [%0], [%1], 16;\n"
                 :: "r"(d), "l"(__cvta_generic_to_global(s)));
}
__device__ __forceinline__ void cp_commit() {
    asm volatile("cp.async.commit_group;\n" ::: "memory");
}
template <int N> __device__ __forceinline__ void cp_wait() {
    asm volatile("cp.async.wait_group %0;\n" :: "n"(N) : "memory");
}

__device__ __forceinline__ void ldm_x4(uint32_t& r0, uint32_t& r1,
                                       uint32_t& r2, uint32_t& r3, uint32_t a) {
    asm volatile("ldmatrix.sync.aligned.m8n8.x4.shared.b16 {%0,%1,%2,%3}, [%4];"
                 : "=r"(r0), "=r"(r1), "=r"(r2), "=r"(r3) : "r"(a));
}

__device__ __forceinline__ void mma_bf16(float* d, uint32_t a0, uint32_t a1,
                                         uint32_t a2, uint32_t a3,
                                         uint32_t b0, uint32_t b1) {
    asm volatile(
        "mma.sync.aligned.m16n8k16.row.col.f32.bf16.bf16.f32 "
        "{%0,%1,%2,%3}, {%4,%5,%6,%7}, {%8,%9}, {%0,%1,%2,%3};"
        : "+f"(d[0]), "+f"(d[1]), "+f"(d[2]), "+f"(d[3])
        : "r"(a0), "r"(a1), "r"(a2), "r"(a3), "r"(b0), "r"(b1));
}

__device__ __forceinline__ uint32_t fkey(float f) {
    uint32_t u = __float_as_uint(f);
    return (u & 0x80000000u) ? ~u : (u | 0x80000000u);
}
__device__ __forceinline__ float fdec(uint32_t k) {
    uint32_t u = (k & 0x80000000u) ? (k ^ 0x80000000u) : ~k;
    return __uint_as_float(u);
}

// ---------------------------------------------------------------------------
// fp32 -> bf16 (codebook only)
// ---------------------------------------------------------------------------
__global__ void tobf16_kernel(const float* __restrict__ in,
                              __nv_bfloat16* __restrict__ outp, int n4) {
    int i = blockIdx.x * blockDim.x + threadIdx.x;
    if (i >= n4) return;
    float4 v = ((const float4*)in)[i];
    ((__nv_bfloat162*)outp)[2 * i]     = __floats2bfloat162_rn(v.x, v.y);
    ((__nv_bfloat162*)outp)[2 * i + 1] = __floats2bfloat162_rn(v.z, v.w);
}

// ---------------------------------------------------------------------------
// c2[n] = ||codebook[n]||^2, exact fp32
// ---------------------------------------------------------------------------
__global__ void c2_kernel(const float* __restrict__ cb, int N) {
    int warp = (blockIdx.x * blockDim.x + threadIdx.x) >> 5;
    int lane = threadIdx.x & 31;
    if (warp >= N) return;
    const float4* row = (const float4*)(cb + (size_t)warp * DIM);
    float s = 0.f;
#pragma unroll
    for (int i = 0; i < 2; i++) {
        float4 v = row[lane + i * 32];
        s += v.x * v.x + v.y * v.y + v.z * v.z + v.w * v.w;
    }
#pragma unroll
    for (int o = 16; o > 0; o >>= 1) s += __shfl_xor_sync(0xffffffffu, s, o);
    if (lane == 0) g_c2[warp] = s;
}

// ---------------------------------------------------------------------------
// Main fused kernel: bf16 HMMA over full N per CTA + margin-band candidate
// tracking + exact fp32 rescore + gather + SSE partial.
// 512 threads = 16 warps (4M x 4N), warp tile 32x32, K=256.
// ---------------------------------------------------------------------------
__global__ void __launch_bounds__(512, 1)
vq_main_kernel(const float* __restrict__ x, const float* __restrict__ cb,
               float* __restrict__ out_q, float* __restrict__ out_idx) {
    extern __shared__ char smraw[];
    const uint32_t sb0   = smem_u32(smraw);
    const uint32_t sbase = (sb0 + 1023) & ~1023u;
    char* smp = smraw + (sbase - sb0);

    const uint32_t sA = sbase + OFF_A;
    uint32_t* rowkey = (uint32_t*)(smp + OFF_KEY);
    int*      cnt    = (int*)     (smp + OFF_CNT);
    int*      cand   = (int*)     (smp + OFF_CAND);

    const int tid  = threadIdx.x;
    const int wid  = tid >> 5;
    const int lane = tid & 31;
    const int m0   = blockIdx.x * M_CTA;
    const int wm   = (wid & 3) * 32;
    const int wn   = (wid >> 2) * 32;
    const int lrow = lane & 15;
    const int lcol = (lane >> 4) << 4;
    const int g    = lane >> 2;
    const int tg   = lane & 3;

    if (tid < 128) { rowkey[tid] = 0xFFFFFFFFu; cnt[tid] = 0; }

    // ---- Stage A: x fp32 -> bf16 into 4 swizzled 16KB planes -------------
#pragma unroll
    for (int i = 0; i < 16; i++) {
        int f   = tid + (i << 9);          // 0..8191 float4s
        int row = f >> 6;                  // 64 float4 per row
        int c4  = f & 63;
        float4 v = ((const float4*)(x + (size_t)(m0 + row) * DIM))[c4];
        __nv_bfloat162 p0 = __floats2bfloat162_rn(v.x, v.y);
        __nv_bfloat162 p1 = __floats2bfloat162_rn(v.z, v.w);
        int plane = c4 >> 4;
        uint32_t off = SWZ((uint32_t)(row * 128 + (c4 & 15) * 8));
        *(uint2*)(smp + OFF_A + plane * 16384 + off) =
            make_uint2(*(uint32_t*)&p0, *(uint32_t*)&p1);
    }

    // ---- Stage B tile 0 ----------------------------------------------------
    {
        uint32_t bb = sbase + OFF_B;
#pragma unroll
        for (int i = 0; i < 8; i++) {
            int idx   = tid + (i << 9);    // 0..4095
            int c16   = idx & 7;
            int plane = (idx >> 3) & 3;
            int row   = idx >> 5;
            cp16(bb + plane * 16384 + SWZ((uint32_t)(row * 128 + c16 * 16)),
                 g_cbb + (size_t)row * DIM + plane * 64 + c16 * 8);
        }
        cp_commit();
    }

    // ---- Main loop over 16 n-tiles ----------------------------------------
    for (int nt = 0; nt < N_TILES; nt++) {
        const int n0 = nt * 128;
        cp_wait<0>();
        __syncthreads();   // tile nt ready; also orders A-stage & row-state init

        if (nt + 1 < N_TILES) {
            uint32_t bb = sbase + OFF_B + ((nt + 1) & 1) * 65536;
            const int nn0 = (nt + 1) * 128;
#pragma unroll
            for (int i = 0; i < 8; i++) {
                int idx   = tid + (i << 9);
                int c16   = idx & 7;
                int plane = (idx >> 3) & 3;
                int row   = idx >> 5;
                cp16(bb + plane * 16384 + SWZ((uint32_t)(row * 128 + c16 * 16)),
                     g_cbb + (size_t)(nn0 + row) * DIM + plane * 64 + c16 * 8);
            }
            cp_commit();
        }

        const uint32_t sB = sbase + OFF_B + (nt & 1) * 65536;

        float acc[2][4][4];
#pragma unroll
        for (int a = 0; a < 2; a++)
#pragma unroll
            for (int b = 0; b < 4; b++)
#pragma unroll
                for (int c = 0; c < 4; c++) acc[a][b][c] = 0.f;

#pragma unroll
        for (int ks = 0; ks < 16; ks++) {
            const uint32_t pa = sA + (ks >> 2) * 16384;
            const uint32_t pb = sB + (ks >> 2) * 16384;
            const int kb = (ks & 3) * 32 + lcol;
            uint32_t a0[4], a1[4], b0[4], b1[4];
            ldm_x4(a0[0], a0[1], a0[2], a0[3],
                   pa + SWZ((uint32_t)((wm + lrow) * 128 + kb)));
            ldm_x4(a1[0], a1[1], a1[2], a1[3],
                   pa + SWZ((uint32_t)((wm + 16 + lrow) * 128 + kb)));
            ldm_x4(b0[0], b0[1], b0[2], b0[3],
                   pb + SWZ((uint32_t)((wn + lrow) * 128 + kb)));
            ldm_x4(b1[0], b1[1], b1[2], b1[3],
                   pb + SWZ((uint32_t)((wn + 16 + lrow) * 128 + kb)));
            mma_bf16(acc[0][0], a0[0], a0[1], a0[2], a0[3], b0[0], b0[2]);
            mma_bf16(acc[0][1], a0[0], a0[1], a0[2], a0[3], b0[1], b0[3]);
            mma_bf16(acc[0][2], a0[0], a0[1], a0[2], a0[3], b1[0], b1[2]);
            mma_bf16(acc[0][3], a0[0], a0[1], a0[2], a0[3], b1[1], b1[3]);
            mma_bf16(acc[1][0], a1[0], a1[1], a1[2], a1[3], b0[0], b0[2]);
            mma_bf16(acc[1][1], a1[0], a1[1], a1[2], a1[3], b0[1], b0[3]);
            mma_bf16(acc[1][2], a1[0], a1[1], a1[2], a1[3], b1[0], b1[2]);
            mma_bf16(acc[1][3], a1[0], a1[1], a1[2], a1[3], b1[1], b1[3]);
        }

        // ---- Epilogue: running min + candidate collection ------------------
        float c2r[4][2];
#pragma unroll
        for (int jn = 0; jn < 4; jn++)
#pragma unroll
            for (int q = 0; q < 2; q++)
                c2r[jn][q] = __ldg(&g_c2[n0 + wn + jn * 8 + tg * 2 + q]);

#pragma unroll
        for (int im = 0; im < 2; im++)
#pragma unroll
            for (int h = 0; h < 2; h++) {
                int r = wm + im * 16 + h * 8 + g;
                float mn = 3.4e38f;
#pragma unroll
                for (int jn = 0; jn < 4; jn++)
#pragma unroll
                    for (int q = 0; q < 2; q++) {
                        float s = fmaf(-2.f, acc[im][jn][h * 2 + q], c2r[jn][q]);
                        mn = fminf(mn, s);
                    }
                atomicMin(&rowkey[r], fkey(mn));
            }
        __syncthreads();

#pragma unroll
        for (int im = 0; im < 2; im++)
#pragma unroll
            for (int h = 0; h < 2; h++) {
                int r = wm + im * 16 + h * 8 + g;
                float thr = fdec(rowkey[r]) + MARGIN;
#pragma unroll
                for (int jn = 0; jn < 4; jn++)
#pragma unroll
                    for (int q = 0; q < 2; q++) {
                        float s = fmaf(-2.f, acc[im][jn][h * 2 + q], c2r[jn][q]);
                        if (s < thr) {
                            int p = atomicAdd(&cnt[r], 1);
                            if (p < CAP) cand[r * CAP + p] = n0 + wn + jn * 8 + tg * 2 + q;
                        }
                    }
            }
        // no sync needed: races only shrink the false-positive set
    }

    __syncthreads();   // all cnt/cand final

    // ---- Exact fp32 rescore + gather + SSE partial (1 warp per row) -------
    for (int r = wid; r < M_CTA; r += 16) {
        const int row = m0 + r;
        const int c = cnt[r];
        const bool ovf = (c > CAP);
        if (lane == 0) g_flag[row] = ovf ? 1 : 0;
        if (ovf) continue;

        const float4* xr = (const float4*)(x + (size_t)row * DIM);
        float4 xv0 = xr[lane * 2], xv1 = xr[lane * 2 + 1];

        float bv = 3.4e38f;
        int   bi = 0x7fffffff;
        for (int ci = 0; ci < c; ci++) {
            int n = cand[r * CAP + ci];
            const float4* cr = (const float4*)(cb + (size_t)n * DIM);
            float4 c0 = cr[lane * 2], c1 = cr[lane * 2 + 1];
            float dot = xv0.x * c0.x + xv0.y * c0.y + xv0.z * c0.z + xv0.w * c0.w
                      + xv1.x * c1.x + xv1.y * c1.y + xv1.z * c1.z + xv1.w * c1.w;
#pragma unroll
            for (int o = 16; o > 0; o >>= 1)
                dot += __shfl_xor_sync(0xffffffffu, dot, o);
            float s = __ldg(&g_c2[n]) - 2.f * dot;
            if (s < bv || (s == bv && n < bi)) { bv = s; bi = n; }
        }

        const float4* cr = (const float4*)(cb + (size_t)bi * DIM);
        float4 c0 = cr[lane * 2], c1 = cr[lane * 2 + 1];
        float4* qr = (float4*)(out_q + (size_t)row * DIM);
        qr[lane * 2]     = c0;
        qr[lane * 2 + 1] = c1;

        float dx = xv0.x - c0.x, dy = xv0.y - c0.y, dz = xv0.z - c0.z, dw = xv0.w - c0.w;
        float d = dx * dx + dy * dy + dz * dz + dw * dw;
        dx = xv1.x - c1.x; dy = xv1.y - c1.y; dz = xv1.z - c1.z; dw = xv1.w - c1.w;
        d += dx * dx + dy * dy + dz * dz + dw * dw;
#pragma unroll
        for (int o = 16; o > 0; o >>= 1) d += __shfl_xor_sync(0xffffffffu, d, o);
        if (lane == 0) {
            g_partial[row] = d;
            out_idx[row]   = (float)bi;
        }
    }
}

// ---------------------------------------------------------------------------
// Rescue: full exact rescan for overflowed rows (rare). 1 warp per token.
// Also performs gather + partial for those rows.
// ---------------------------------------------------------------------------
__global__ void __launch_bounds__(1024)
rescue_kernel(const float* __restrict__ x, const float* __restrict__ cb,
              float* __restrict__ out_q, float* __restrict__ out_idx, int N) {
    const int wid = threadIdx.x >> 5, lane = threadIdx.x & 31;
    const int t = blockIdx.x * 32 + wid;
    if (g_flag[t] == 0) return;

    const float4* xr = (const float4*)(x + (size_t)t * DIM);
    float4 xv0 = xr[lane * 2], xv1 = xr[lane * 2 + 1];
    __shared__ float xs[32][DIM / 32 + 1];   // unused padding scheme avoided

    float bv = 3.4e38f;
    int   bi = 0x7fffffff;
    for (int n = 0; n < N; n++) {
        const float4* cr = (const float4*)(cb + (size_t)n * DIM);
        float4 c0 = cr[lane * 2], c1 = cr[lane * 2 + 1];
        float dot = xv0.x * c0.x + xv0.y * c0.y + xv0.z * c0.z + xv0.w * c0.w
                  + xv1.x * c1.x + xv1.y * c1.y + xv1.z * c1.z + xv1.w * c1.w;
#pragma unroll
        for (int o = 16; o > 0; o >>= 1)
            dot += __shfl_xor_sync(0xffffffffu, dot, o);
        float s = __ldg(&g_c2[n]) - 2.f * dot;
        if (s < bv || (s == bv && n < bi)) { bv = s; bi = n; }
    }

    const float4* cr = (const float4*)(cb + (size_t)bi * DIM);
    float4 c0 = cr[lane * 2], c1 = cr[lane * 2 + 1];
    float4* qr = (float4*)(out_q + (size_t)t * DIM);
    qr[lane * 2]     = c0;
    qr[lane * 2 + 1] = c1;

    float dx = xv0.x - c0.x, dy = xv0.y - c0.y, dz = xv0.z - c0.z, dw = xv0.w - c0.w;
    float d = dx * dx + dy * dy + dz * dz + dw * dw;
    dx = xv1.x - c1.x; dy = xv1.y - c1.y; dz = xv1.z - c1.z; dw = xv1.w - c1.w;
    d += dx * dx + dy * dy + dz * dz + dw * dw;
#pragma unroll
    for (int o = 16; o > 0; o >>= 1) d += __shfl_xor_sync(0xffffffffu, d, o);
    if (lane == 0) {
        g_partial[t] = d;
        out_idx[t]   = (float)bi;
    }
}

// ---------------------------------------------------------------------------
// Deterministic loss reduction: loss = 2 * mean((x - codes)^2)
// ---------------------------------------------------------------------------
__global__ void loss_kernel(float* __restrict__ out_loss, int n4, float inv_count) {
    __shared__ float red[32];
    const int tid = threadIdx.x;
    float s = 0.f;
    const float4* p4 = (const float4*)g_partial;
    for (int i = tid; i < n4; i += 1024) {
        float4 v = p4[i];
        s += v.x + v.y + v.z + v.w;
    }
#pragma unroll
    for (int o = 16; o > 0; o >>= 1) s += __shfl_xor_sync(0xffffffffu, s, o);
    if ((tid & 31) == 0) red[tid >> 5] = s;
    __syncthreads();
    if (tid < 32) {
        float v = red[tid];
#pragma unroll
        for (int o = 16; o > 0; o >>= 1) v += __shfl_xor_sync(0xffffffffu, v, o);
        if (tid == 0) *out_loss = 2.f * v * inv_count;
    }
}

// ---------------------------------------------------------------------------
extern "C" void kernel_launch(void* const* d_in, const int* in_sizes, int n_in,
                              void* d_out, int out_size) {
    const float* x  = (const float*)d_in[0];
    const float* cb = (const float*)d_in[1];
    float* out = (float*)d_out;

    const int bt = in_sizes[0] / DIM;   // 32768
    const int nc = in_sizes[1] / DIM;   // 2048

    const long long need = (long long)bt * DIM + bt + 1;
    const bool full_layout = ((long long)out_size >= need);
    float* out_idx  = full_layout ? (out + (size_t)bt * DIM) : g_dummy;
    float* out_loss = full_layout ? (out + (size_t)bt * DIM + bt) : (g_dummy + BT);

    __nv_bfloat16* cbb;
    cudaGetSymbolAddress((void**)&cbb, g_cbb);

    const int nc4 = nc * DIM / 4;
    tobf16_kernel<<<(nc4 + 255) / 256, 256>>>(cb, cbb, nc4);
    c2_kernel<<<(nc + 7) / 8, 256>>>(cb, nc);

    cudaFuncSetAttribute(vq_main_kernel,
                         cudaFuncAttributeMaxDynamicSharedMemorySize, SMEM_BYTES);
    vq_main_kernel<<<bt / M_CTA, 512, SMEM_BYTES>>>(x, cb, out, out_idx);

    rescue_kernel<<<bt / 32, 1024>>>(x, cb, out, out_idx, nc);
    loss_kernel<<<1, 1024>>>(out_loss, bt / 4, 1.f / ((float)bt * (float)DIM));
}